// round 8
// baseline (speedup 1.0000x reference)
#include <cuda_runtime.h>
#include <cuda_bf16.h>
#include <cstdint>

#define B_WIN   2048
#define NTOK    64
#define DIM     256
#define NHEADS  8
#define QKVDIM  768
#define MROWS   (B_WIN * NTOK)          // 131072
#define SCALE   0.17677669529663687f    // 32^-0.5

// ---------------- scratch (device globals; no cudaMalloc allowed) ----------
#define HEAD_ELEMS (2048ull * 8ull * 64ull * 32ull)   // 33.5M per plane
__device__ __nv_bfloat16 g_q_hi[HEAD_ELEMS],  g_q_lo[HEAD_ELEMS];
__device__ __nv_bfloat16 g_k_hi[HEAD_ELEMS],  g_k_lo[HEAD_ELEMS];
__device__ __nv_bfloat16 g_vt_hi[HEAD_ELEMS], g_vt_lo[HEAD_ELEMS];  // [bh][d][n]
__device__ __nv_bfloat16 g_x_hi[(size_t)MROWS * DIM];
__device__ __nv_bfloat16 g_x_lo[(size_t)MROWS * DIM];
__device__ __nv_bfloat16 g_ao_hi[(size_t)MROWS * DIM];
__device__ __nv_bfloat16 g_ao_lo[(size_t)MROWS * DIM];
__device__ __nv_bfloat16 g_wq_hi[QKVDIM * DIM];
__device__ __nv_bfloat16 g_wq_lo[QKVDIM * DIM];
__device__ __nv_bfloat16 g_wp_hi[DIM * DIM];
__device__ __nv_bfloat16 g_wp_lo[DIM * DIM];

// ================= helpers ==================================================
__device__ __forceinline__ uint32_t smem_u32(const void* p) {
    uint32_t a;
    asm("{ .reg .u64 t; cvta.to.shared.u64 t, %1; cvt.u32.u64 %0, t; }"
        : "=r"(a) : "l"(p));
    return a;
}

__device__ __forceinline__ void ldsm_x4(uint32_t* r, uint32_t addr) {
    asm volatile("ldmatrix.sync.aligned.m8n8.x4.shared.b16 {%0,%1,%2,%3}, [%4];"
                 : "=r"(r[0]), "=r"(r[1]), "=r"(r[2]), "=r"(r[3]) : "r"(addr));
}

// D += A(bf16 16x16) * B(bf16 16x8), fp32 accumulate
__device__ __forceinline__ void mma16816(float* c, const uint32_t* a, const uint32_t* b) {
    asm volatile("mma.sync.aligned.m16n8k16.row.col.f32.bf16.bf16.f32 "
                 "{%0,%1,%2,%3}, {%4,%5,%6,%7}, {%8,%9}, {%0,%1,%2,%3};"
                 : "+f"(c[0]), "+f"(c[1]), "+f"(c[2]), "+f"(c[3])
                 : "r"(a[0]), "r"(a[1]), "r"(a[2]), "r"(a[3]),
                   "r"(b[0]), "r"(b[1]));
}

__device__ __forceinline__ uint32_t pack_bf16x2(float x, float y) {
    __nv_bfloat162 t = __floats2bfloat162_rn(x, y);
    return *(uint32_t*)&t;
}

__device__ __forceinline__ void cp16(uint32_t dst, const void* src) {
    asm volatile("cp.async.cg.shared.global [%0], [%1], 16;"
                 :: "r"(dst), "l"(src) : "memory");
}
#define CP_COMMIT() asm volatile("cp.async.commit_group;" ::: "memory")

// ================= fp32 -> (hi, lo) bf16 split =============================
__global__ void convert_split(const float* __restrict__ src,
                              __nv_bfloat16* __restrict__ hi,
                              __nv_bfloat16* __restrict__ lo, int n4)
{
    int i = blockIdx.x * blockDim.x + threadIdx.x;
    if (i >= n4) return;
    float4 v = ((const float4*)src)[i];
    float f[4] = {v.x, v.y, v.z, v.w};
    __nv_bfloat16 h[4], l[4];
#pragma unroll
    for (int k = 0; k < 4; k++) {
        h[k] = __float2bfloat16(f[k]);
        l[k] = __float2bfloat16(f[k] - __bfloat162float(h[k]));
    }
    ((__nv_bfloat162*)hi)[2*i]   = __halves2bfloat162(h[0], h[1]);
    ((__nv_bfloat162*)hi)[2*i+1] = __halves2bfloat162(h[2], h[3]);
    ((__nv_bfloat162*)lo)[2*i]   = __halves2bfloat162(l[0], l[1]);
    ((__nv_bfloat162*)lo)[2*i+1] = __halves2bfloat162(l[2], l[3]);
}

// ================= HMMA GEMM (cp.async, 128x128 block, warp tile 32x64) ====
// C[128 x 128] = A[128 x 256] * W[128 x 256]^T  (3-term bf16 split)
// 8 warps: 4(M) x 2(N), warp tile 32x64, BK=32, 2 async stages.
// mma issued TERM-MAJOR within each B-group: same-acc reuse distance = 4
// (breaks the RAW chain that capped tensor pipe at ~54%).

#define SROWB   80                  // bytes per smem row (40 bf16, conflict-free)
#define OFF_AH  0
#define OFF_AL  10240
#define OFF_BH  20480
#define OFF_BL  30720
#define STAGE   40960
#define GEMM_SMEM (2 * STAGE)       // 81920 bytes

template <int MODE>
__global__ void __launch_bounds__(256, 2)
gemm_mma(const __nv_bfloat16* __restrict__ Ah, const __nv_bfloat16* __restrict__ Al,
         const __nv_bfloat16* __restrict__ Wh, const __nv_bfloat16* __restrict__ Wl,
         const float* __restrict__ bias, float* __restrict__ out)
{
    extern __shared__ char smem[];
    const uint32_t sb = smem_u32(smem);

    const int tid  = threadIdx.x;
    const int lane = tid & 31;
    const int warp = tid >> 5;
    const int wm   = warp >> 1;          // 0..3
    const int wn   = warp & 1;           // 0..1
    const int row0 = blockIdx.y * 128;
    const int col0 = blockIdx.x * 128;

    float acc[2][8][4];
#pragma unroll
    for (int a = 0; a < 2; a++)
#pragma unroll
        for (int b = 0; b < 8; b++)
#pragma unroll
            for (int c = 0; c < 4; c++) acc[a][b][c] = 0.f;

    const int lrow = tid >> 2;
    const int lc4  = (tid & 3);
    const uint32_t so_base = (uint32_t)lrow * SROWB + lc4 * 16;

    const int a_row  = wm * 32 + (lane & 15);
    const int a_ksel = (lane >> 4) * 8;
    const int b_rowb = wn * 64 + ((lane >> 4) << 3) + (lane & 7);
    const int b_ksel = ((lane >> 3) & 1) << 3;

    auto issue = [&](int kc, uint32_t stb) {
        const int k0 = kc * 32;
#pragma unroll
        for (int t = 0; t < 2; t++) {
            const int r = lrow + t * 64;
            const uint32_t so = so_base + t * 64 * SROWB;
            const size_t ga = (size_t)(row0 + r) * 256 + k0 + lc4 * 8;
            const size_t gb = (size_t)(col0 + r) * 256 + k0 + lc4 * 8;
            cp16(stb + OFF_AH + so, Ah + ga);
            cp16(stb + OFF_AL + so, Al + ga);
            cp16(stb + OFF_BH + so, Wh + gb);
            cp16(stb + OFF_BL + so, Wl + gb);
        }
    };

    issue(0, sb);
    CP_COMMIT();

    for (int kc = 0; kc < 8; kc++) {
        if (kc < 7) {
            issue(kc + 1, sb + ((kc + 1) & 1) * STAGE);
            CP_COMMIT();
            asm volatile("cp.async.wait_group 1;" ::: "memory");
        } else {
            asm volatile("cp.async.wait_group 0;" ::: "memory");
        }
        __syncthreads();

        const uint32_t stb = sb + (kc & 1) * STAGE;
#pragma unroll
        for (int kk = 0; kk < 32; kk += 16) {
            uint32_t a_h[2][4], a_l[2][4];
#pragma unroll
            for (int mt = 0; mt < 2; mt++) {
                const uint32_t off = (uint32_t)(a_row + mt * 16) * SROWB
                                   + (kk + a_ksel) * 2;
                ldsm_x4(a_h[mt], stb + OFF_AH + off);
                ldsm_x4(a_l[mt], stb + OFF_AL + off);
            }
#pragma unroll
            for (int g = 0; g < 4; g++) {
                uint32_t b_h[4], b_l[4];
                const uint32_t off = (uint32_t)(b_rowb + g * 16) * SROWB
                                   + (kk + b_ksel) * 2;
                ldsm_x4(b_h, stb + OFF_BH + off);
                ldsm_x4(b_l, stb + OFF_BL + off);
                // term-major: 4 independent accs between same-acc reuses
#pragma unroll
                for (int mt = 0; mt < 2; mt++)
#pragma unroll
                    for (int j = 0; j < 2; j++)
                        mma16816(acc[mt][g * 2 + j], a_h[mt], &b_h[j * 2]);
#pragma unroll
                for (int mt = 0; mt < 2; mt++)
#pragma unroll
                    for (int j = 0; j < 2; j++)
                        mma16816(acc[mt][g * 2 + j], a_h[mt], &b_l[j * 2]);
#pragma unroll
                for (int mt = 0; mt < 2; mt++)
#pragma unroll
                    for (int j = 0; j < 2; j++)
                        mma16816(acc[mt][g * 2 + j], a_l[mt], &b_h[j * 2]);
            }
        }
        __syncthreads();
    }

    // ---- epilogue -------------------------------------------------------------
    const int gid = lane >> 2, tig = lane & 3;
#pragma unroll
    for (int mt = 0; mt < 2; mt++)
#pragma unroll
        for (int g = 0; g < 4; g++)
#pragma unroll
            for (int j = 0; j < 2; j++) {
                const int nf = g * 2 + j;
                const int col = col0 + wn * 64 + g * 16 + j * 8 + tig * 2;
                const float2 bv = *(const float2*)(bias + col);
#pragma unroll
                for (int rs = 0; rs < 2; rs++) {
                    const int row = row0 + wm * 32 + mt * 16 + gid + rs * 8;
                    float v0 = acc[mt][nf][rs * 2 + 0] + bv.x;
                    float v1 = acc[mt][nf][rs * 2 + 1] + bv.y;
                    if (MODE == 0) {
                        const int s = col >> 8;
                        if (s == 0) { v0 *= SCALE; v1 *= SCALE; }
                        __nv_bfloat16 h0 = __float2bfloat16(v0);
                        __nv_bfloat16 l0 = __float2bfloat16(v0 - __bfloat162float(h0));
                        __nv_bfloat16 h1 = __float2bfloat16(v1);
                        __nv_bfloat16 l1 = __float2bfloat16(v1 - __bfloat162float(h1));
                        const int hh = (col >> 5) & 7, d = col & 31;
                        const int b = row >> 6, n = row & 63;
                        const size_t pb = (size_t)(b * 8 + hh) * 2048;
                        if (s == 0) {
                            *(__nv_bfloat162*)(g_q_hi + pb + n * 32 + d) = __halves2bfloat162(h0, h1);
                            *(__nv_bfloat162*)(g_q_lo + pb + n * 32 + d) = __halves2bfloat162(l0, l1);
                        } else if (s == 1) {
                            *(__nv_bfloat162*)(g_k_hi + pb + n * 32 + d) = __halves2bfloat162(h0, h1);
                            *(__nv_bfloat162*)(g_k_lo + pb + n * 32 + d) = __halves2bfloat162(l0, l1);
                        } else {   // v, stored transposed [d][n]
                            g_vt_hi[pb + (size_t)d * 64 + n]       = h0;
                            g_vt_hi[pb + (size_t)(d + 1) * 64 + n] = h1;
                            g_vt_lo[pb + (size_t)d * 64 + n]       = l0;
                            g_vt_lo[pb + (size_t)(d + 1) * 64 + n] = l1;
                        }
                    } else {
                        *(float2*)(out + (size_t)row * 256 + col)
                            = make_float2(v0, v1);
                    }
                }
            }
}

// ================= HMMA attention: one (window, head) per CTA ===============
#define QSTR 40
#define VSTR 72

__global__ void __launch_bounds__(128)
attn_mma(const float* __restrict__ mask, const float* __restrict__ bias_table)
{
    const int bh = blockIdx.x;
    const int b  = bh >> 3;
    const int h  = bh & 7;

    __shared__ __nv_bfloat16 sQh[64 * QSTR], sQl[64 * QSTR];
    __shared__ __nv_bfloat16 sKh[64 * QSTR], sKl[64 * QSTR];
    __shared__ __nv_bfloat16 sVh[32 * VSTR], sVl[32 * VSTR];
    __shared__ float bt[228];

    const int tid  = threadIdx.x;
    const int warp = tid >> 5;
    const int lane = tid & 31;

    const __nv_bfloat16* Qh = g_q_hi  + (size_t)bh * 2048;
    const __nv_bfloat16* Ql = g_q_lo  + (size_t)bh * 2048;
    const __nv_bfloat16* Kh = g_k_hi  + (size_t)bh * 2048;
    const __nv_bfloat16* Kl = g_k_lo  + (size_t)bh * 2048;
    const __nv_bfloat16* Vh = g_vt_hi + (size_t)bh * 2048;
    const __nv_bfloat16* Vl = g_vt_lo + (size_t)bh * 2048;

    for (int c = tid; c < 256; c += 128) {
        const int qr = c >> 2, qc = (c & 3) * 8;
        *(uint4*)(sQh + qr * QSTR + qc) = *(const uint4*)(Qh + c * 8);
        *(uint4*)(sQl + qr * QSTR + qc) = *(const uint4*)(Ql + c * 8);
        *(uint4*)(sKh + qr * QSTR + qc) = *(const uint4*)(Kh + c * 8);
        *(uint4*)(sKl + qr * QSTR + qc) = *(const uint4*)(Kl + c * 8);
        const int vr = c >> 3, vc = (c & 7) * 8;
        *(uint4*)(sVh + vr * VSTR + vc) = *(const uint4*)(Vh + c * 8);
        *(uint4*)(sVl + vr * VSTR + vc) = *(const uint4*)(Vl + c * 8);
    }
    for (int t = tid; t < 225; t += 128) bt[t] = bias_table[t * NHEADS + h];
    __syncthreads();

    const int gid = lane >> 2, tig = lane & 3;
    const int a_rowoff = (warp * 16 + (lane & 15)) * QSTR + (lane >> 4) * 8;
    const int b_row    = ((lane >> 4) << 3) + (lane & 7);
    const int b_ksel   = ((lane >> 3) & 1) << 3;

    // ---- QK^T (term-major mma ordering) ----------------------------------------
    float acc[8][4];
#pragma unroll
    for (int nt = 0; nt < 8; nt++)
#pragma unroll
        for (int c = 0; c < 4; c++) acc[nt][c] = 0.f;

#pragma unroll
    for (int kt = 0; kt < 2; kt++) {
        uint32_t qh[4], ql[4];
        ldsm_x4(qh, smem_u32(sQh + a_rowoff + kt * 16));
        ldsm_x4(ql, smem_u32(sQl + a_rowoff + kt * 16));
        uint32_t kh[4][4], kl[4][4];
#pragma unroll
        for (int ng = 0; ng < 4; ng++) {
            const int off = (ng * 16 + b_row) * QSTR + kt * 16 + b_ksel;
            ldsm_x4(kh[ng], smem_u32(sKh + off));
            ldsm_x4(kl[ng], smem_u32(sKl + off));
        }
#pragma unroll
        for (int ng = 0; ng < 4; ng++)
#pragma unroll
            for (int j = 0; j < 2; j++)
                mma16816(acc[ng * 2 + j], qh, &kh[ng][j * 2]);
#pragma unroll
        for (int ng = 0; ng < 4; ng++)
#pragma unroll
            for (int j = 0; j < 2; j++)
                mma16816(acc[ng * 2 + j], qh, &kl[ng][j * 2]);
#pragma unroll
        for (int ng = 0; ng < 4; ng++)
#pragma unroll
            for (int j = 0; j < 2; j++)
                mma16816(acc[ng * 2 + j], ql, &kh[ng][j * 2]);
    }

    // ---- bias + mask ----------------------------------------------------------
    const int i0 = warp * 16 + gid, i1 = i0 + 8;
    const int yi0 = i0 >> 3, xi0 = i0 & 7;
    const int yi1 = i1 >> 3, xi1 = i1 & 7;
    const float* mrow = mask + (size_t)b * 4096;
#pragma unroll
    for (int nt = 0; nt < 8; nt++) {
        const int col = nt * 8 + tig * 2;
        const float2 m0 = *(const float2*)(mrow + i0 * 64 + col);
        const float2 m1 = *(const float2*)(mrow + i1 * 64 + col);
        acc[nt][0] += bt[(yi0 - nt + 7) * 15 + (xi0 - tig * 2 + 7)] + m0.x;
        acc[nt][1] += bt[(yi0 - nt + 7) * 15 + (xi0 - tig * 2 + 6)] + m0.y;
        acc[nt][2] += bt[(yi1 - nt + 7) * 15 + (xi1 - tig * 2 + 7)] + m1.x;
        acc[nt][3] += bt[(yi1 - nt + 7) * 15 + (xi1 - tig * 2 + 6)] + m1.y;
    }

    // ---- softmax ---------------------------------------------------------------
    float mx0 = -1e30f, mx1 = -1e30f;
#pragma unroll
    for (int nt = 0; nt < 8; nt++) {
        mx0 = fmaxf(mx0, fmaxf(acc[nt][0], acc[nt][1]));
        mx1 = fmaxf(mx1, fmaxf(acc[nt][2], acc[nt][3]));
    }
    mx0 = fmaxf(mx0, __shfl_xor_sync(0xffffffffu, mx0, 1));
    mx0 = fmaxf(mx0, __shfl_xor_sync(0xffffffffu, mx0, 2));
    mx1 = fmaxf(mx1, __shfl_xor_sync(0xffffffffu, mx1, 1));
    mx1 = fmaxf(mx1, __shfl_xor_sync(0xffffffffu, mx1, 2));

    float sum0 = 0.f, sum1 = 0.f;
#pragma unroll
    for (int nt = 0; nt < 8; nt++) {
        acc[nt][0] = __expf(acc[nt][0] - mx0);
        acc[nt][1] = __expf(acc[nt][1] - mx0);
        acc[nt][2] = __expf(acc[nt][2] - mx1);
        acc[nt][3] = __expf(acc[nt][3] - mx1);
        sum0 += acc[nt][0] + acc[nt][1];
        sum1 += acc[nt][2] + acc[nt][3];
    }
    sum0 += __shfl_xor_sync(0xffffffffu, sum0, 1);
    sum0 += __shfl_xor_sync(0xffffffffu, sum0, 2);
    sum1 += __shfl_xor_sync(0xffffffffu, sum1, 1);
    sum1 += __shfl_xor_sync(0xffffffffu, sum1, 2);
    const float inv0 = 1.f / sum0, inv1 = 1.f / sum1;

    // ---- repack P into A-fragments (hi/lo split) --------------------------------
    uint32_t phi[4][4], plo[4][4];
#pragma unroll
    for (int kt = 0; kt < 4; kt++) {
        const float f[4][2] = {
            {acc[kt*2][0] * inv0,   acc[kt*2][1] * inv0},
            {acc[kt*2][2] * inv1,   acc[kt*2][3] * inv1},
            {acc[kt*2+1][0] * inv0, acc[kt*2+1][1] * inv0},
            {acc[kt*2+1][2] * inv1, acc[kt*2+1][3] * inv1}};
#pragma unroll
        for (int r = 0; r < 4; r++) {
            __nv_bfloat16 hx = __float2bfloat16(f[r][0]);
            __nv_bfloat16 hy = __float2bfloat16(f[r][1]);
            phi[kt][r] = pack_bf16x2(f[r][0], f[r][1]);
            plo[kt][r] = pack_bf16x2(f[r][0] - __bfloat162float(hx),
                                     f[r][1] - __bfloat162float(hy));
        }
    }

    // ---- P * V (term-major) -------------------------------------------------------
    float ao[4][4];
#pragma unroll
    for (int dn = 0; dn < 4; dn++)
#pragma unroll
        for (int c = 0; c < 4; c++) ao[dn][c] = 0.f;

#pragma unroll
    for (int kt = 0; kt < 4; kt++) {
        uint32_t vh[2][4], vl[2][4];
#pragma unroll
        for (int g = 0; g < 2; g++) {
            const int off = (g * 16 + b_row) * VSTR + kt * 16 + b_ksel;
            ldsm_x4(vh[g], smem_u32(sVh + off));
            ldsm_x4(vl[g], smem_u32(sVl + off));
        }
#pragma unroll
        for (int g = 0; g < 2; g++)
#pragma unroll
            for (int j = 0; j < 2; j++)
                mma16816(ao[g * 2 + j], phi[kt], &vh[g][j * 2]);
#pragma unroll
        for (int g = 0; g < 2; g++)
#pragma unroll
            for (int j = 0; j < 2; j++)
                mma16816(ao[g * 2 + j], phi[kt], &vl[g][j * 2]);
#pragma unroll
        for (int g = 0; g < 2; g++)
#pragma unroll
            for (int j = 0; j < 2; j++)
                mma16816(ao[g * 2 + j], plo[kt], &vh[g][j * 2]);
    }

    // ---- epilogue --------------------------------------------------------------
#pragma unroll
    for (int dn = 0; dn < 4; dn++) {
        const int d = dn * 8 + tig * 2;
#pragma unroll
        for (int rs = 0; rs < 2; rs++) {
            const int row = rs ? i1 : i0;
            const float v0 = ao[dn][rs * 2 + 0];
            const float v1 = ao[dn][rs * 2 + 1];
            __nv_bfloat16 h0 = __float2bfloat16(v0);
            __nv_bfloat16 l0 = __float2bfloat16(v0 - __bfloat162float(h0));
            __nv_bfloat16 h1 = __float2bfloat16(v1);
            __nv_bfloat16 l1 = __float2bfloat16(v1 - __bfloat162float(h1));
            const size_t o = ((size_t)b * 64 + row) * DIM + h * 32 + d;
            *(__nv_bfloat162*)(g_ao_hi + o) = __halves2bfloat162(h0, h1);
            *(__nv_bfloat162*)(g_ao_lo + o) = __halves2bfloat162(l0, l1);
        }
    }
}

// ---------------- launch ----------------------------------------------------
extern "C" void kernel_launch(void* const* d_in, const int* in_sizes, int n_in,
                              void* d_out, int out_size)
{
    const float* x          = (const float*)d_in[0]; // (2048,64,256)
    const float* mask       = (const float*)d_in[1]; // (2048,1,64,64)
    const float* w_qkv      = (const float*)d_in[2]; // (768,256)
    const float* b_qkv      = (const float*)d_in[3]; // (768)
    const float* w_proj     = (const float*)d_in[4]; // (256,256)
    const float* b_proj     = (const float*)d_in[5]; // (256)
    const float* bias_table = (const float*)d_in[6]; // (225,8)
    float* out = (float*)d_out;                      // (2048,64,256)

    (void)in_sizes; (void)n_in; (void)out_size;

    __nv_bfloat16 *xh, *xl, *wqh, *wql, *wph, *wpl, *aoh, *aol;
    cudaGetSymbolAddress((void**)&xh,  g_x_hi);
    cudaGetSymbolAddress((void**)&xl,  g_x_lo);
    cudaGetSymbolAddress((void**)&wqh, g_wq_hi);
    cudaGetSymbolAddress((void**)&wql, g_wq_lo);
    cudaGetSymbolAddress((void**)&wph, g_wp_hi);
    cudaGetSymbolAddress((void**)&wpl, g_wp_lo);
    cudaGetSymbolAddress((void**)&aoh, g_ao_hi);
    cudaGetSymbolAddress((void**)&aol, g_ao_lo);

    cudaFuncSetAttribute(gemm_mma<0>, cudaFuncAttributeMaxDynamicSharedMemorySize, GEMM_SMEM);
    cudaFuncSetAttribute(gemm_mma<1>, cudaFuncAttributeMaxDynamicSharedMemorySize, GEMM_SMEM);

    // 0) fp32 -> bf16 hi/lo splits
    {
        int n4 = (MROWS * DIM) / 4;
        convert_split<<<(n4 + 255) / 256, 256>>>(x, xh, xl, n4);
        int w4 = (QKVDIM * DIM) / 4;
        convert_split<<<(w4 + 255) / 256, 256>>>(w_qkv, wqh, wql, w4);
        int p4 = (DIM * DIM) / 4;
        convert_split<<<(p4 + 255) / 256, 256>>>(w_proj, wph, wpl, p4);
    }
    // 1) QKV GEMM (HMMA, cp.async) -> q/k/vt bf16 hi/lo planes (q pre-scaled)
    {
        dim3 grid(QKVDIM / 128, MROWS / 128);   // 6 x 1024
        gemm_mma<0><<<grid, 256, GEMM_SMEM>>>(xh, xl, wqh, wql, b_qkv, nullptr);
    }
    // 2) windowed attention (HMMA) -> g_ao hi/lo
    attn_mma<<<B_WIN * NHEADS, 128>>>(mask, bias_table);
    // 3) output projection (HMMA, cp.async) -> out
    {
        dim3 grid(DIM / 128, MROWS / 128);      // 2 x 1024
        gemm_mma<1><<<grid, 256, GEMM_SMEM>>>(aoh, aol, wph, wpl, b_proj, out);
    }
}

// round 9
// speedup vs baseline: 1.1908x; 1.1908x over previous
#include <cuda_runtime.h>
#include <cuda_bf16.h>
#include <cstdint>

#define B_WIN   2048
#define NTOK    64
#define DIM     256
#define NHEADS  8
#define QKVDIM  768
#define MROWS   (B_WIN * NTOK)          // 131072
#define SCALE   0.17677669529663687f    // 32^-0.5

// ---------------- scratch (device globals; no cudaMalloc allowed) ----------
#define HEAD_ELEMS (2048ull * 8ull * 64ull * 32ull)
__device__ __nv_bfloat16 g_q_hi[HEAD_ELEMS],  g_q_lo[HEAD_ELEMS];
__device__ __nv_bfloat16 g_k_hi[HEAD_ELEMS],  g_k_lo[HEAD_ELEMS];
__device__ __nv_bfloat16 g_vt_hi[HEAD_ELEMS], g_vt_lo[HEAD_ELEMS];  // [bh][d][n]
__device__ float g_xr[(size_t)MROWS * DIM];    // tf32-rounded x
__device__ float g_ao[(size_t)MROWS * DIM];    // tf32-rounded attention out
__device__ float g_wqr[QKVDIM * DIM];          // tf32-rounded w_qkv
__device__ float g_wpr[DIM * DIM];             // tf32-rounded w_proj

// ================= helpers ==================================================
__device__ __forceinline__ uint32_t smem_u32(const void* p) {
    uint32_t a;
    asm("{ .reg .u64 t; cvta.to.shared.u64 t, %1; cvt.u32.u64 %0, t; }"
        : "=r"(a) : "l"(p));
    return a;
}

__device__ __forceinline__ void ldsm_x4(uint32_t* r, uint32_t addr) {
    asm volatile("ldmatrix.sync.aligned.m8n8.x4.shared.b16 {%0,%1,%2,%3}, [%4];"
                 : "=r"(r[0]), "=r"(r[1]), "=r"(r[2]), "=r"(r[3]) : "r"(addr));
}

// bf16 k16 mma (attention path)
__device__ __forceinline__ void mma16816(float* c, const uint32_t* a, const uint32_t* b) {
    asm volatile("mma.sync.aligned.m16n8k16.row.col.f32.bf16.bf16.f32 "
                 "{%0,%1,%2,%3}, {%4,%5,%6,%7}, {%8,%9}, {%0,%1,%2,%3};"
                 : "+f"(c[0]), "+f"(c[1]), "+f"(c[2]), "+f"(c[3])
                 : "r"(a[0]), "r"(a[1]), "r"(a[2]), "r"(a[3]),
                   "r"(b[0]), "r"(b[1]));
}

// tf32 k8 mma (GEMM path)
__device__ __forceinline__ void mma1688(float* c, const uint32_t* a,
                                        uint32_t b0, uint32_t b1) {
    asm volatile("mma.sync.aligned.m16n8k8.row.col.f32.tf32.tf32.f32 "
                 "{%0,%1,%2,%3}, {%4,%5,%6,%7}, {%8,%9}, {%0,%1,%2,%3};"
                 : "+f"(c[0]), "+f"(c[1]), "+f"(c[2]), "+f"(c[3])
                 : "r"(a[0]), "r"(a[1]), "r"(a[2]), "r"(a[3]),
                   "r"(b0), "r"(b1));
}

__device__ __forceinline__ float tf32r(float f) {
    uint32_t u;
    asm("cvt.rna.tf32.f32 %0, %1;" : "=r"(u) : "f"(f));
    return __uint_as_float(u);
}

__device__ __forceinline__ uint32_t pack_bf16x2(float x, float y) {
    __nv_bfloat162 t = __floats2bfloat162_rn(x, y);
    return *(uint32_t*)&t;
}

__device__ __forceinline__ void cp16(uint32_t dst, const void* src) {
    asm volatile("cp.async.cg.shared.global [%0], [%1], 16;"
                 :: "r"(dst), "l"(src) : "memory");
}
#define CP_COMMIT() asm volatile("cp.async.commit_group;" ::: "memory")

// ================= fp32 -> tf32-rounded fp32 ================================
__global__ void round_tf32(const float* __restrict__ src,
                           float* __restrict__ dst, int n4)
{
    int i = blockIdx.x * blockDim.x + threadIdx.x;
    if (i >= n4) return;
    float4 v = ((const float4*)src)[i];
    v.x = tf32r(v.x); v.y = tf32r(v.y); v.z = tf32r(v.z); v.w = tf32r(v.w);
    ((float4*)dst)[i] = v;
}

// ================= TF32 GEMM (cp.async, 128x128 block, warp tile 32x64) ====
// C[128 x 128] = A[128 x 256] * W[128 x 256]^T  (1-pass tf32, pre-rounded)
// 8 warps: 4(M) x 2(N), warp tile 32x64, BK=32, 2 async stages.
// MODE 0: epilogue splits into q/k/vt bf16 hi/lo planes (q scaled).
// MODE 1: writes fp32 `out`.

#define TSTRW  36                   // fp32 words per smem row (144B, conflict-free)
#define T_A    0
#define T_B    18432                // 128*36*4
#define TSTAGE 36864
#define TGEMM_SMEM (2 * TSTAGE)     // 73728 bytes

template <int MODE>
__global__ void __launch_bounds__(256, 2)
gemm_tf32(const float* __restrict__ A, const float* __restrict__ W,
          const float* __restrict__ bias, float* __restrict__ out)
{
    extern __shared__ char smem[];
    const uint32_t sb = smem_u32(smem);

    const int tid  = threadIdx.x;
    const int lane = tid & 31;
    const int warp = tid >> 5;
    const int wm   = warp >> 1;          // 0..3
    const int wn   = warp & 1;           // 0..1
    const int row0 = blockIdx.y * 128;
    const int col0 = blockIdx.x * 128;

    float acc[2][8][4];
#pragma unroll
    for (int a = 0; a < 2; a++)
#pragma unroll
        for (int b = 0; b < 8; b++)
#pragma unroll
            for (int c = 0; c < 4; c++) acc[a][b][c] = 0.f;

    const int gid = lane >> 2, tig = lane & 3;

    auto issue = [&](int kc, uint32_t stb) {
        const int k0 = kc * 32;
#pragma unroll
        for (int t = 0; t < 4; t++) {
            const int idx = tid + t * 256;
            const int r = idx >> 3, c8 = idx & 7;
            const uint32_t so = (uint32_t)r * 144 + c8 * 16;
            cp16(stb + T_A + so, A + (size_t)(row0 + r) * 256 + k0 + c8 * 4);
            cp16(stb + T_B + so, W + (size_t)(col0 + r) * 256 + k0 + c8 * 4);
        }
    };

    issue(0, sb);
    CP_COMMIT();

    const int aw = (wm * 32 + gid) * TSTRW;     // A row base (words)
    const int bw = (wn * 64 + gid) * TSTRW;     // B row base (words)

    for (int kc = 0; kc < 8; kc++) {
        if (kc < 7) {
            issue(kc + 1, sb + ((kc + 1) & 1) * TSTAGE);
            CP_COMMIT();
            asm volatile("cp.async.wait_group 1;" ::: "memory");
        } else {
            asm volatile("cp.async.wait_group 0;" ::: "memory");
        }
        __syncthreads();

        const uint32_t* sA = (const uint32_t*)(smem + (kc & 1) * TSTAGE + T_A);
        const uint32_t* sB = (const uint32_t*)(smem + (kc & 1) * TSTAGE + T_B);

#pragma unroll
        for (int ks = 0; ks < 4; ks++) {
            const int kcol = ks * 8 + tig;
            uint32_t af[2][4];
#pragma unroll
            for (int mt = 0; mt < 2; mt++) {
                const int rb = aw + mt * 16 * TSTRW;
                af[mt][0] = sA[rb + kcol];
                af[mt][1] = sA[rb + 8 * TSTRW + kcol];
                af[mt][2] = sA[rb + kcol + 4];
                af[mt][3] = sA[rb + 8 * TSTRW + kcol + 4];
            }
#pragma unroll
            for (int nt = 0; nt < 8; nt++) {
                const int nb = bw + nt * 8 * TSTRW;
                const uint32_t b0 = sB[nb + kcol];
                const uint32_t b1 = sB[nb + kcol + 4];
                mma1688(acc[0][nt], af[0], b0, b1);
                mma1688(acc[1][nt], af[1], b0, b1);
            }
        }
        __syncthreads();
    }

    // ---- epilogue -------------------------------------------------------------
#pragma unroll
    for (int mt = 0; mt < 2; mt++)
#pragma unroll
        for (int nt = 0; nt < 8; nt++) {
            const int col = col0 + wn * 64 + nt * 8 + tig * 2;
            const float2 bv = *(const float2*)(bias + col);
#pragma unroll
            for (int rs = 0; rs < 2; rs++) {
                const int row = row0 + wm * 32 + mt * 16 + gid + rs * 8;
                float v0 = acc[mt][nt][rs * 2 + 0] + bv.x;
                float v1 = acc[mt][nt][rs * 2 + 1] + bv.y;
                if (MODE == 0) {
                    const int s = col >> 8;
                    if (s == 0) { v0 *= SCALE; v1 *= SCALE; }
                    __nv_bfloat16 h0 = __float2bfloat16(v0);
                    __nv_bfloat16 l0 = __float2bfloat16(v0 - __bfloat162float(h0));
                    __nv_bfloat16 h1 = __float2bfloat16(v1);
                    __nv_bfloat16 l1 = __float2bfloat16(v1 - __bfloat162float(h1));
                    const int hh = (col >> 5) & 7, d = col & 31;
                    const int b = row >> 6, n = row & 63;
                    const size_t pb = (size_t)(b * 8 + hh) * 2048;
                    if (s == 0) {
                        *(__nv_bfloat162*)(g_q_hi + pb + n * 32 + d) = __halves2bfloat162(h0, h1);
                        *(__nv_bfloat162*)(g_q_lo + pb + n * 32 + d) = __halves2bfloat162(l0, l1);
                    } else if (s == 1) {
                        *(__nv_bfloat162*)(g_k_hi + pb + n * 32 + d) = __halves2bfloat162(h0, h1);
                        *(__nv_bfloat162*)(g_k_lo + pb + n * 32 + d) = __halves2bfloat162(l0, l1);
                    } else {   // v, stored transposed [d][n]
                        g_vt_hi[pb + (size_t)d * 64 + n]       = h0;
                        g_vt_hi[pb + (size_t)(d + 1) * 64 + n] = h1;
                        g_vt_lo[pb + (size_t)d * 64 + n]       = l0;
                        g_vt_lo[pb + (size_t)(d + 1) * 64 + n] = l1;
                    }
                } else {
                    *(float2*)(out + (size_t)row * 256 + col)
                        = make_float2(v0, v1);
                }
            }
        }
}

// ================= HMMA attention: one (window, head) per CTA ===============
#define QSTR 40
#define VSTR 72

__global__ void __launch_bounds__(128)
attn_mma(const float* __restrict__ mask, const float* __restrict__ bias_table)
{
    const int bh = blockIdx.x;
    const int b  = bh >> 3;
    const int h  = bh & 7;

    __shared__ __nv_bfloat16 sQh[64 * QSTR], sQl[64 * QSTR];
    __shared__ __nv_bfloat16 sKh[64 * QSTR], sKl[64 * QSTR];
    __shared__ __nv_bfloat16 sVh[32 * VSTR], sVl[32 * VSTR];
    __shared__ float bt[228];

    const int tid  = threadIdx.x;
    const int warp = tid >> 5;
    const int lane = tid & 31;

    const __nv_bfloat16* Qh = g_q_hi  + (size_t)bh * 2048;
    const __nv_bfloat16* Ql = g_q_lo  + (size_t)bh * 2048;
    const __nv_bfloat16* Kh = g_k_hi  + (size_t)bh * 2048;
    const __nv_bfloat16* Kl = g_k_lo  + (size_t)bh * 2048;
    const __nv_bfloat16* Vh = g_vt_hi + (size_t)bh * 2048;
    const __nv_bfloat16* Vl = g_vt_lo + (size_t)bh * 2048;

    for (int c = tid; c < 256; c += 128) {
        const int qr = c >> 2, qc = (c & 3) * 8;
        *(uint4*)(sQh + qr * QSTR + qc) = *(const uint4*)(Qh + c * 8);
        *(uint4*)(sQl + qr * QSTR + qc) = *(const uint4*)(Ql + c * 8);
        *(uint4*)(sKh + qr * QSTR + qc) = *(const uint4*)(Kh + c * 8);
        *(uint4*)(sKl + qr * QSTR + qc) = *(const uint4*)(Kl + c * 8);
        const int vr = c >> 3, vc = (c & 7) * 8;
        *(uint4*)(sVh + vr * VSTR + vc) = *(const uint4*)(Vh + c * 8);
        *(uint4*)(sVl + vr * VSTR + vc) = *(const uint4*)(Vl + c * 8);
    }
    for (int t = tid; t < 225; t += 128) bt[t] = bias_table[t * NHEADS + h];
    __syncthreads();

    const int gid = lane >> 2, tig = lane & 3;
    const int a_rowoff = (warp * 16 + (lane & 15)) * QSTR + (lane >> 4) * 8;
    const int b_row    = ((lane >> 4) << 3) + (lane & 7);
    const int b_ksel   = ((lane >> 3) & 1) << 3;

    // ---- QK^T ------------------------------------------------------------------
    float acc[8][4];
#pragma unroll
    for (int nt = 0; nt < 8; nt++)
#pragma unroll
        for (int c = 0; c < 4; c++) acc[nt][c] = 0.f;

#pragma unroll
    for (int kt = 0; kt < 2; kt++) {
        uint32_t qh[4], ql[4];
        ldsm_x4(qh, smem_u32(sQh + a_rowoff + kt * 16));
        ldsm_x4(ql, smem_u32(sQl + a_rowoff + kt * 16));
#pragma unroll
        for (int ng = 0; ng < 4; ng++) {
            uint32_t kh[4], kl[4];
            const int off = (ng * 16 + b_row) * QSTR + kt * 16 + b_ksel;
            ldsm_x4(kh, smem_u32(sKh + off));
            ldsm_x4(kl, smem_u32(sKl + off));
#pragma unroll
            for (int j = 0; j < 2; j++) {
                float* c = acc[ng * 2 + j];
                mma16816(c, qh, &kh[j * 2]);
                mma16816(c, qh, &kl[j * 2]);
                mma16816(c, ql, &kh[j * 2]);
            }
        }
    }

    // ---- bias + mask ----------------------------------------------------------
    const int i0 = warp * 16 + gid, i1 = i0 + 8;
    const int yi0 = i0 >> 3, xi0 = i0 & 7;
    const int yi1 = i1 >> 3, xi1 = i1 & 7;
    const float* mrow = mask + (size_t)b * 4096;
#pragma unroll
    for (int nt = 0; nt < 8; nt++) {
        const int col = nt * 8 + tig * 2;
        const float2 m0 = *(const float2*)(mrow + i0 * 64 + col);
        const float2 m1 = *(const float2*)(mrow + i1 * 64 + col);
        acc[nt][0] += bt[(yi0 - nt + 7) * 15 + (xi0 - tig * 2 + 7)] + m0.x;
        acc[nt][1] += bt[(yi0 - nt + 7) * 15 + (xi0 - tig * 2 + 6)] + m0.y;
        acc[nt][2] += bt[(yi1 - nt + 7) * 15 + (xi1 - tig * 2 + 7)] + m1.x;
        acc[nt][3] += bt[(yi1 - nt + 7) * 15 + (xi1 - tig * 2 + 6)] + m1.y;
    }

    // ---- softmax ---------------------------------------------------------------
    float mx0 = -1e30f, mx1 = -1e30f;
#pragma unroll
    for (int nt = 0; nt < 8; nt++) {
        mx0 = fmaxf(mx0, fmaxf(acc[nt][0], acc[nt][1]));
        mx1 = fmaxf(mx1, fmaxf(acc[nt][2], acc[nt][3]));
    }
    mx0 = fmaxf(mx0, __shfl_xor_sync(0xffffffffu, mx0, 1));
    mx0 = fmaxf(mx0, __shfl_xor_sync(0xffffffffu, mx0, 2));
    mx1 = fmaxf(mx1, __shfl_xor_sync(0xffffffffu, mx1, 1));
    mx1 = fmaxf(mx1, __shfl_xor_sync(0xffffffffu, mx1, 2));

    float sum0 = 0.f, sum1 = 0.f;
#pragma unroll
    for (int nt = 0; nt < 8; nt++) {
        acc[nt][0] = __expf(acc[nt][0] - mx0);
        acc[nt][1] = __expf(acc[nt][1] - mx0);
        acc[nt][2] = __expf(acc[nt][2] - mx1);
        acc[nt][3] = __expf(acc[nt][3] - mx1);
        sum0 += acc[nt][0] + acc[nt][1];
        sum1 += acc[nt][2] + acc[nt][3];
    }
    sum0 += __shfl_xor_sync(0xffffffffu, sum0, 1);
    sum0 += __shfl_xor_sync(0xffffffffu, sum0, 2);
    sum1 += __shfl_xor_sync(0xffffffffu, sum1, 1);
    sum1 += __shfl_xor_sync(0xffffffffu, sum1, 2);
    const float inv0 = 1.f / sum0, inv1 = 1.f / sum1;

    // ---- repack P into A-fragments (hi/lo split) --------------------------------
    uint32_t phi[4][4], plo[4][4];
#pragma unroll
    for (int kt = 0; kt < 4; kt++) {
        const float f[4][2] = {
            {acc[kt*2][0] * inv0,   acc[kt*2][1] * inv0},
            {acc[kt*2][2] * inv1,   acc[kt*2][3] * inv1},
            {acc[kt*2+1][0] * inv0, acc[kt*2+1][1] * inv0},
            {acc[kt*2+1][2] * inv1, acc[kt*2+1][3] * inv1}};
#pragma unroll
        for (int r = 0; r < 4; r++) {
            __nv_bfloat16 hx = __float2bfloat16(f[r][0]);
            __nv_bfloat16 hy = __float2bfloat16(f[r][1]);
            phi[kt][r] = pack_bf16x2(f[r][0], f[r][1]);
            plo[kt][r] = pack_bf16x2(f[r][0] - __bfloat162float(hx),
                                     f[r][1] - __bfloat162float(hy));
        }
    }

    // ---- P * V -------------------------------------------------------------------
    float ao[4][4];
#pragma unroll
    for (int dn = 0; dn < 4; dn++)
#pragma unroll
        for (int c = 0; c < 4; c++) ao[dn][c] = 0.f;

#pragma unroll
    for (int kt = 0; kt < 4; kt++) {
#pragma unroll
        for (int g = 0; g < 2; g++) {
            uint32_t vh[4], vl[4];
            const int off = (g * 16 + b_row) * VSTR + kt * 16 + b_ksel;
            ldsm_x4(vh, smem_u32(sVh + off));
            ldsm_x4(vl, smem_u32(sVl + off));
#pragma unroll
            for (int j = 0; j < 2; j++) {
                float* c = ao[g * 2 + j];
                mma16816(c, phi[kt], &vh[j * 2]);
                mma16816(c, phi[kt], &vl[j * 2]);
                mma16816(c, plo[kt], &vh[j * 2]);
            }
        }
    }

    // ---- epilogue: tf32-rounded fp32 for the proj GEMM --------------------------
#pragma unroll
    for (int dn = 0; dn < 4; dn++) {
        const int d = dn * 8 + tig * 2;
#pragma unroll
        for (int rs = 0; rs < 2; rs++) {
            const int row = rs ? i1 : i0;
            const float v0 = tf32r(ao[dn][rs * 2 + 0]);
            const float v1 = tf32r(ao[dn][rs * 2 + 1]);
            const size_t o = ((size_t)b * 64 + row) * DIM + h * 32 + d;
            *(float2*)(g_ao + o) = make_float2(v0, v1);
        }
    }
}

// ---------------- launch ----------------------------------------------------
extern "C" void kernel_launch(void* const* d_in, const int* in_sizes, int n_in,
                              void* d_out, int out_size)
{
    const float* x          = (const float*)d_in[0]; // (2048,64,256)
    const float* mask       = (const float*)d_in[1]; // (2048,1,64,64)
    const float* w_qkv      = (const float*)d_in[2]; // (768,256)
    const float* b_qkv      = (const float*)d_in[3]; // (768)
    const float* w_proj     = (const float*)d_in[4]; // (256,256)
    const float* b_proj     = (const float*)d_in[5]; // (256)
    const float* bias_table = (const float*)d_in[6]; // (225,8)
    float* out = (float*)d_out;                      // (2048,64,256)

    (void)in_sizes; (void)n_in; (void)out_size;

    float *xr, *ao, *wqr, *wpr;
    cudaGetSymbolAddress((void**)&xr,  g_xr);
    cudaGetSymbolAddress((void**)&ao,  g_ao);
    cudaGetSymbolAddress((void**)&wqr, g_wqr);
    cudaGetSymbolAddress((void**)&wpr, g_wpr);

    cudaFuncSetAttribute(gemm_tf32<0>, cudaFuncAttributeMaxDynamicSharedMemorySize, TGEMM_SMEM);
    cudaFuncSetAttribute(gemm_tf32<1>, cudaFuncAttributeMaxDynamicSharedMemorySize, TGEMM_SMEM);

    // 0) round operands to tf32 (removes truncation bias in the mma)
    {
        int n4 = (MROWS * DIM) / 4;
        round_tf32<<<(n4 + 255) / 256, 256>>>(x, xr, n4);
        int w4 = (QKVDIM * DIM) / 4;
        round_tf32<<<(w4 + 255) / 256, 256>>>(w_qkv, wqr, w4);
        int p4 = (DIM * DIM) / 4;
        round_tf32<<<(p4 + 255) / 256, 256>>>(w_proj, wpr, p4);
    }
    // 1) QKV GEMM (tf32) -> q/k/vt bf16 hi/lo planes (q pre-scaled)
    {
        dim3 grid(QKVDIM / 128, MROWS / 128);   // 6 x 1024
        gemm_tf32<0><<<grid, 256, TGEMM_SMEM>>>(xr, wqr, b_qkv, nullptr);
    }
    // 2) windowed attention (bf16 HMMA) -> g_ao (tf32-rounded fp32)
    attn_mma<<<B_WIN * NHEADS, 128>>>(mask, bias_table);
    // 3) output projection (tf32) -> out
    {
        dim3 grid(DIM / 128, MROWS / 128);      // 2 x 1024
        gemm_tf32<1><<<grid, 256, TGEMM_SMEM>>>(ao, wpr, b_proj, out);
    }
}

// round 10
// speedup vs baseline: 1.2496x; 1.0493x over previous
#include <cuda_runtime.h>
#include <cuda_bf16.h>
#include <cstdint>

#define B_WIN   2048
#define NTOK    64
#define DIM     256
#define NHEADS  8
#define QKVDIM  768
#define MROWS   (B_WIN * NTOK)          // 131072
#define SCALE   0.17677669529663687f    // 32^-0.5

// ---------------- scratch (device globals; no cudaMalloc allowed) ----------
#define HEAD_ELEMS (2048ull * 8ull * 64ull * 32ull)
__device__ __nv_bfloat16 g_q_hi[HEAD_ELEMS],  g_q_lo[HEAD_ELEMS];
__device__ __nv_bfloat16 g_k_hi[HEAD_ELEMS],  g_k_lo[HEAD_ELEMS];
__device__ __nv_bfloat16 g_vt_hi[HEAD_ELEMS], g_vt_lo[HEAD_ELEMS];  // [bh][d][n]
__device__ float g_xr[(size_t)MROWS * DIM];    // tf32-rounded x
__device__ float g_ao[(size_t)MROWS * DIM];    // tf32-rounded attention out
__device__ float g_wqr[QKVDIM * DIM];          // tf32-rounded w_qkv
__device__ float g_wpr[DIM * DIM];             // tf32-rounded w_proj

// ================= helpers ==================================================
__device__ __forceinline__ uint32_t smem_u32(const void* p) {
    uint32_t a;
    asm("{ .reg .u64 t; cvta.to.shared.u64 t, %1; cvt.u32.u64 %0, t; }"
        : "=r"(a) : "l"(p));
    return a;
}

__device__ __forceinline__ void ldsm_x4(uint32_t* r, uint32_t addr) {
    asm volatile("ldmatrix.sync.aligned.m8n8.x4.shared.b16 {%0,%1,%2,%3}, [%4];"
                 : "=r"(r[0]), "=r"(r[1]), "=r"(r[2]), "=r"(r[3]) : "r"(addr));
}

// bf16 k16 mma (attention path)
__device__ __forceinline__ void mma16816(float* c, const uint32_t* a, const uint32_t* b) {
    asm volatile("mma.sync.aligned.m16n8k16.row.col.f32.bf16.bf16.f32 "
                 "{%0,%1,%2,%3}, {%4,%5,%6,%7}, {%8,%9}, {%0,%1,%2,%3};"
                 : "+f"(c[0]), "+f"(c[1]), "+f"(c[2]), "+f"(c[3])
                 : "r"(a[0]), "r"(a[1]), "r"(a[2]), "r"(a[3]),
                   "r"(b[0]), "r"(b[1]));
}

// tf32 k8 mma (GEMM path)
__device__ __forceinline__ void mma1688(float* c, const uint32_t* a,
                                        uint32_t b0, uint32_t b1) {
    asm volatile("mma.sync.aligned.m16n8k8.row.col.f32.tf32.tf32.f32 "
                 "{%0,%1,%2,%3}, {%4,%5,%6,%7}, {%8,%9}, {%0,%1,%2,%3};"
                 : "+f"(c[0]), "+f"(c[1]), "+f"(c[2]), "+f"(c[3])
                 : "r"(a[0]), "r"(a[1]), "r"(a[2]), "r"(a[3]),
                   "r"(b0), "r"(b1));
}

__device__ __forceinline__ float tf32r(float f) {
    uint32_t u;
    asm("cvt.rna.tf32.f32 %0, %1;" : "=r"(u) : "f"(f));
    return __uint_as_float(u);
}

__device__ __forceinline__ uint32_t pack_bf16x2(float x, float y) {
    __nv_bfloat162 t = __floats2bfloat162_rn(x, y);
    return *(uint32_t*)&t;
}

__device__ __forceinline__ void cp16(uint32_t dst, const void* src) {
    asm volatile("cp.async.cg.shared.global [%0], [%1], 16;"
                 :: "r"(dst), "l"(src) : "memory");
}
#define CP_COMMIT() asm volatile("cp.async.commit_group;" ::: "memory")

// ================= fp32 -> tf32-rounded fp32 ================================
__global__ void round_tf32(const float* __restrict__ src,
                           float* __restrict__ dst, int n4)
{
    int i = blockIdx.x * blockDim.x + threadIdx.x;
    if (i >= n4) return;
    float4 v = ((const float4*)src)[i];
    v.x = tf32r(v.x); v.y = tf32r(v.y); v.z = tf32r(v.z); v.w = tf32r(v.w);
    ((float4*)dst)[i] = v;
}

// ================= TF32 GEMM (cp.async + LDSM fragments) ====================
// C[128 x 128] = A[128 x 256] * W[128 x 256]^T  (1-pass tf32, pre-rounded)
// 8 warps: 4(M) x 2(N), warp tile 32x64, BK=32, 2 async stages.
// Fragments via ldmatrix.b16 (tf32 word mapping == m16n8k8 fragment layout):
// 6 LDSM.x4 + 16 mma per ks step (was 24 LDS.32 + 16 mma).

#define TSTRW  36                   // fp32 words per smem row (144B, conflict-free)
#define T_A    0
#define T_B    18432                // 128*36*4
#define TSTAGE 36864
#define TGEMM_SMEM (2 * TSTAGE)     // 73728 bytes

template <int MODE>
__global__ void __launch_bounds__(256, 2)
gemm_tf32(const float* __restrict__ A, const float* __restrict__ W,
          const float* __restrict__ bias, float* __restrict__ out)
{
    extern __shared__ char smem[];
    const uint32_t sb = smem_u32(smem);

    const int tid  = threadIdx.x;
    const int lane = tid & 31;
    const int warp = tid >> 5;
    const int wm   = warp >> 1;          // 0..3
    const int wn   = warp & 1;           // 0..1
    const int row0 = blockIdx.y * 128;
    const int col0 = blockIdx.x * 128;

    float acc[2][8][4];
#pragma unroll
    for (int a = 0; a < 2; a++)
#pragma unroll
        for (int b = 0; b < 8; b++)
#pragma unroll
            for (int c = 0; c < 4; c++) acc[a][b][c] = 0.f;

    const int gid = lane >> 2, tig = lane & 3;

    auto issue = [&](int kc, uint32_t stb) {
        const int k0 = kc * 32;
#pragma unroll
        for (int t = 0; t < 4; t++) {
            const int idx = tid + t * 256;
            const int r = idx >> 3, c8 = idx & 7;
            const uint32_t so = (uint32_t)r * 144 + c8 * 16;
            cp16(stb + T_A + so, A + (size_t)(row0 + r) * 256 + k0 + c8 * 4);
            cp16(stb + T_B + so, W + (size_t)(col0 + r) * 256 + k0 + c8 * 4);
        }
    };

    issue(0, sb);
    CP_COMMIT();

    // ldsm lane addressing (see header comment):
    // A matrices: (rows 0-7 / 8-15) x (k 0-3 / 4-7)  -> a0,a1,a2,a3 order
    // B matrices: (rows 0-7: k 0-3, k 4-7), (rows 8-15: k 0-3, k 4-7)
    const int lg = lane >> 3, lrw = lane & 7;
    const uint32_t a_ld = (uint32_t)((wm * 32 + ((lg & 1) << 3) + lrw) * TSTRW
                                     + ((lg >> 1) << 2)) * 4;
    const uint32_t b_ld = (uint32_t)((wn * 64 + ((lg >> 1) << 3) + lrw) * TSTRW
                                     + ((lg & 1) << 2)) * 4;

    for (int kc = 0; kc < 8; kc++) {
        if (kc < 7) {
            issue(kc + 1, sb + ((kc + 1) & 1) * TSTAGE);
            CP_COMMIT();
            asm volatile("cp.async.wait_group 1;" ::: "memory");
        } else {
            asm volatile("cp.async.wait_group 0;" ::: "memory");
        }
        __syncthreads();

        const uint32_t sA = sb + (kc & 1) * TSTAGE + T_A;
        const uint32_t sB = sb + (kc & 1) * TSTAGE + T_B;

#pragma unroll
        for (int ks = 0; ks < 4; ks++) {
            const uint32_t kso = (uint32_t)(ks * 8) * 4;   // k word offset in bytes
            uint32_t af[2][4], bf[4][4];
#pragma unroll
            for (int mt = 0; mt < 2; mt++)
                ldsm_x4(af[mt], sA + a_ld + mt * 16 * TSTRW * 4 + kso);
#pragma unroll
            for (int p = 0; p < 4; p++)
                ldsm_x4(bf[p], sB + b_ld + p * 16 * TSTRW * 4 + kso);
            // af[mt] = {a0,a1,a2,a3}; bf[p] = {b0,b1 of nt=2p, b0,b1 of nt=2p+1}
#pragma unroll
            for (int mt = 0; mt < 2; mt++)
#pragma unroll
                for (int nt = 0; nt < 8; nt++) {
                    const uint32_t* bb = &bf[nt >> 1][(nt & 1) * 2];
                    mma1688(acc[mt][nt], af[mt], bb[0], bb[1]);
                }
        }
        __syncthreads();
    }

    // ---- epilogue -------------------------------------------------------------
#pragma unroll
    for (int mt = 0; mt < 2; mt++)
#pragma unroll
        for (int nt = 0; nt < 8; nt++) {
            const int col = col0 + wn * 64 + nt * 8 + tig * 2;
            const float2 bv = *(const float2*)(bias + col);
#pragma unroll
            for (int rs = 0; rs < 2; rs++) {
                const int row = row0 + wm * 32 + mt * 16 + gid + rs * 8;
                float v0 = acc[mt][nt][rs * 2 + 0] + bv.x;
                float v1 = acc[mt][nt][rs * 2 + 1] + bv.y;
                if (MODE == 0) {
                    const int s = col >> 8;
                    if (s == 0) { v0 *= SCALE; v1 *= SCALE; }
                    __nv_bfloat16 h0 = __float2bfloat16(v0);
                    __nv_bfloat16 l0 = __float2bfloat16(v0 - __bfloat162float(h0));
                    __nv_bfloat16 h1 = __float2bfloat16(v1);
                    __nv_bfloat16 l1 = __float2bfloat16(v1 - __bfloat162float(h1));
                    const int hh = (col >> 5) & 7, d = col & 31;
                    const int b = row >> 6, n = row & 63;
                    const size_t pb = (size_t)(b * 8 + hh) * 2048;
                    if (s == 0) {
                        *(__nv_bfloat162*)(g_q_hi + pb + n * 32 + d) = __halves2bfloat162(h0, h1);
                        *(__nv_bfloat162*)(g_q_lo + pb + n * 32 + d) = __halves2bfloat162(l0, l1);
                    } else if (s == 1) {
                        *(__nv_bfloat162*)(g_k_hi + pb + n * 32 + d) = __halves2bfloat162(h0, h1);
                        *(__nv_bfloat162*)(g_k_lo + pb + n * 32 + d) = __halves2bfloat162(l0, l1);
                    } else {   // v, stored transposed [d][n]
                        g_vt_hi[pb + (size_t)d * 64 + n]       = h0;
                        g_vt_hi[pb + (size_t)(d + 1) * 64 + n] = h1;
                        g_vt_lo[pb + (size_t)d * 64 + n]       = l0;
                        g_vt_lo[pb + (size_t)(d + 1) * 64 + n] = l1;
                    }
                } else {
                    *(float2*)(out + (size_t)row * 256 + col)
                        = make_float2(v0, v1);
                }
            }
        }
}

// ================= HMMA attention: one (window, head) per CTA ===============
#define QSTR 40
#define VSTR 72

__global__ void __launch_bounds__(128)
attn_mma(const float* __restrict__ mask, const float* __restrict__ bias_table)
{
    const int bh = blockIdx.x;
    const int b  = bh >> 3;
    const int h  = bh & 7;

    __shared__ __nv_bfloat16 sQh[64 * QSTR], sQl[64 * QSTR];
    __shared__ __nv_bfloat16 sKh[64 * QSTR], sKl[64 * QSTR];
    __shared__ __nv_bfloat16 sVh[32 * VSTR], sVl[32 * VSTR];
    __shared__ float bt[228];

    const int tid  = threadIdx.x;
    const int warp = tid >> 5;
    const int lane = tid & 31;

    const __nv_bfloat16* Qh = g_q_hi  + (size_t)bh * 2048;
    const __nv_bfloat16* Ql = g_q_lo  + (size_t)bh * 2048;
    const __nv_bfloat16* Kh = g_k_hi  + (size_t)bh * 2048;
    const __nv_bfloat16* Kl = g_k_lo  + (size_t)bh * 2048;
    const __nv_bfloat16* Vh = g_vt_hi + (size_t)bh * 2048;
    const __nv_bfloat16* Vl = g_vt_lo + (size_t)bh * 2048;

    for (int c = tid; c < 256; c += 128) {
        const int qr = c >> 2, qc = (c & 3) * 8;
        *(uint4*)(sQh + qr * QSTR + qc) = *(const uint4*)(Qh + c * 8);
        *(uint4*)(sQl + qr * QSTR + qc) = *(const uint4*)(Ql + c * 8);
        *(uint4*)(sKh + qr * QSTR + qc) = *(const uint4*)(Kh + c * 8);
        *(uint4*)(sKl + qr * QSTR + qc) = *(const uint4*)(Kl + c * 8);
        const int vr = c >> 3, vc = (c & 7) * 8;
        *(uint4*)(sVh + vr * VSTR + vc) = *(const uint4*)(Vh + c * 8);
        *(uint4*)(sVl + vr * VSTR + vc) = *(const uint4*)(Vl + c * 8);
    }
    for (int t = tid; t < 225; t += 128) bt[t] = bias_table[t * NHEADS + h];
    __syncthreads();

    const int gid = lane >> 2, tig = lane & 3;
    const int a_rowoff = (warp * 16 + (lane & 15)) * QSTR + (lane >> 4) * 8;
    const int b_row    = ((lane >> 4) << 3) + (lane & 7);
    const int b_ksel   = ((lane >> 3) & 1) << 3;

    // ---- QK^T ------------------------------------------------------------------
    float acc[8][4];
#pragma unroll
    for (int nt = 0; nt < 8; nt++)
#pragma unroll
        for (int c = 0; c < 4; c++) acc[nt][c] = 0.f;

#pragma unroll
    for (int kt = 0; kt < 2; kt++) {
        uint32_t qh[4], ql[4];
        ldsm_x4(qh, smem_u32(sQh + a_rowoff + kt * 16));
        ldsm_x4(ql, smem_u32(sQl + a_rowoff + kt * 16));
#pragma unroll
        for (int ng = 0; ng < 4; ng++) {
            uint32_t kh[4], kl[4];
            const int off = (ng * 16 + b_row) * QSTR + kt * 16 + b_ksel;
            ldsm_x4(kh, smem_u32(sKh + off));
            ldsm_x4(kl, smem_u32(sKl + off));
#pragma unroll
            for (int j = 0; j < 2; j++) {
                float* c = acc[ng * 2 + j];
                mma16816(c, qh, &kh[j * 2]);
                mma16816(c, qh, &kl[j * 2]);
                mma16816(c, ql, &kh[j * 2]);
            }
        }
    }

    // ---- bias + mask ----------------------------------------------------------
    const int i0 = warp * 16 + gid, i1 = i0 + 8;
    const int yi0 = i0 >> 3, xi0 = i0 & 7;
    const int yi1 = i1 >> 3, xi1 = i1 & 7;
    const float* mrow = mask + (size_t)b * 4096;
#pragma unroll
    for (int nt = 0; nt < 8; nt++) {
        const int col = nt * 8 + tig * 2;
        const float2 m0 = *(const float2*)(mrow + i0 * 64 + col);
        const float2 m1 = *(const float2*)(mrow + i1 * 64 + col);
        acc[nt][0] += bt[(yi0 - nt + 7) * 15 + (xi0 - tig * 2 + 7)] + m0.x;
        acc[nt][1] += bt[(yi0 - nt + 7) * 15 + (xi0 - tig * 2 + 6)] + m0.y;
        acc[nt][2] += bt[(yi1 - nt + 7) * 15 + (xi1 - tig * 2 + 7)] + m1.x;
        acc[nt][3] += bt[(yi1 - nt + 7) * 15 + (xi1 - tig * 2 + 6)] + m1.y;
    }

    // ---- softmax ---------------------------------------------------------------
    float mx0 = -1e30f, mx1 = -1e30f;
#pragma unroll
    for (int nt = 0; nt < 8; nt++) {
        mx0 = fmaxf(mx0, fmaxf(acc[nt][0], acc[nt][1]));
        mx1 = fmaxf(mx1, fmaxf(acc[nt][2], acc[nt][3]));
    }
    mx0 = fmaxf(mx0, __shfl_xor_sync(0xffffffffu, mx0, 1));
    mx0 = fmaxf(mx0, __shfl_xor_sync(0xffffffffu, mx0, 2));
    mx1 = fmaxf(mx1, __shfl_xor_sync(0xffffffffu, mx1, 1));
    mx1 = fmaxf(mx1, __shfl_xor_sync(0xffffffffu, mx1, 2));

    float sum0 = 0.f, sum1 = 0.f;
#pragma unroll
    for (int nt = 0; nt < 8; nt++) {
        acc[nt][0] = __expf(acc[nt][0] - mx0);
        acc[nt][1] = __expf(acc[nt][1] - mx0);
        acc[nt][2] = __expf(acc[nt][2] - mx1);
        acc[nt][3] = __expf(acc[nt][3] - mx1);
        sum0 += acc[nt][0] + acc[nt][1];
        sum1 += acc[nt][2] + acc[nt][3];
    }
    sum0 += __shfl_xor_sync(0xffffffffu, sum0, 1);
    sum0 += __shfl_xor_sync(0xffffffffu, sum0, 2);
    sum1 += __shfl_xor_sync(0xffffffffu, sum1, 1);
    sum1 += __shfl_xor_sync(0xffffffffu, sum1, 2);
    const float inv0 = 1.f / sum0, inv1 = 1.f / sum1;

    // ---- repack P into A-fragments (hi/lo split) --------------------------------
    uint32_t phi[4][4], plo[4][4];
#pragma unroll
    for (int kt = 0; kt < 4; kt++) {
        const float f[4][2] = {
            {acc[kt*2][0] * inv0,   acc[kt*2][1] * inv0},
            {acc[kt*2][2] * inv1,   acc[kt*2][3] * inv1},
            {acc[kt*2+1][0] * inv0, acc[kt*2+1][1] * inv0},
            {acc[kt*2+1][2] * inv1, acc[kt*2+1][3] * inv1}};
#pragma unroll
        for (int r = 0; r < 4; r++) {
            __nv_bfloat16 hx = __float2bfloat16(f[r][0]);
            __nv_bfloat16 hy = __float2bfloat16(f[r][1]);
            phi[kt][r] = pack_bf16x2(f[r][0], f[r][1]);
            plo[kt][r] = pack_bf16x2(f[r][0] - __bfloat162float(hx),
                                     f[r][1] - __bfloat162float(hy));
        }
    }

    // ---- P * V -------------------------------------------------------------------
    float ao[4][4];
#pragma unroll
    for (int dn = 0; dn < 4; dn++)
#pragma unroll
        for (int c = 0; c < 4; c++) ao[dn][c] = 0.f;

#pragma unroll
    for (int kt = 0; kt < 4; kt++) {
#pragma unroll
        for (int g = 0; g < 2; g++) {
            uint32_t vh[4], vl[4];
            const int off = (g * 16 + b_row) * VSTR + kt * 16 + b_ksel;
            ldsm_x4(vh, smem_u32(sVh + off));
            ldsm_x4(vl, smem_u32(sVl + off));
#pragma unroll
            for (int j = 0; j < 2; j++) {
                float* c = ao[g * 2 + j];
                mma16816(c, phi[kt], &vh[j * 2]);
                mma16816(c, phi[kt], &vl[j * 2]);
                mma16816(c, plo[kt], &vh[j * 2]);
            }
        }
    }

    // ---- epilogue: tf32-rounded fp32 for the proj GEMM --------------------------
#pragma unroll
    for (int dn = 0; dn < 4; dn++) {
        const int d = dn * 8 + tig * 2;
#pragma unroll
        for (int rs = 0; rs < 2; rs++) {
            const int row = rs ? i1 : i0;
            const float v0 = tf32r(ao[dn][rs * 2 + 0]);
            const float v1 = tf32r(ao[dn][rs * 2 + 1]);
            const size_t o = ((size_t)b * 64 + row) * DIM + h * 32 + d;
            *(float2*)(g_ao + o) = make_float2(v0, v1);
        }
    }
}

// ---------------- launch ----------------------------------------------------
extern "C" void kernel_launch(void* const* d_in, const int* in_sizes, int n_in,
                              void* d_out, int out_size)
{
    const float* x          = (const float*)d_in[0]; // (2048,64,256)
    const float* mask       = (const float*)d_in[1]; // (2048,1,64,64)
    const float* w_qkv      = (const float*)d_in[2]; // (768,256)
    const float* b_qkv      = (const float*)d_in[3]; // (768)
    const float* w_proj     = (const float*)d_in[4]; // (256,256)
    const float* b_proj     = (const float*)d_in[5]; // (256)
    const float* bias_table = (const float*)d_in[6]; // (225,8)
    float* out = (float*)d_out;                      // (2048,64,256)

    (void)in_sizes; (void)n_in; (void)out_size;

    float *xr, *ao, *wqr, *wpr;
    cudaGetSymbolAddress((void**)&xr,  g_xr);
    cudaGetSymbolAddress((void**)&ao,  g_ao);
    cudaGetSymbolAddress((void**)&wqr, g_wqr);
    cudaGetSymbolAddress((void**)&wpr, g_wpr);

    cudaFuncSetAttribute(gemm_tf32<0>, cudaFuncAttributeMaxDynamicSharedMemorySize, TGEMM_SMEM);
    cudaFuncSetAttribute(gemm_tf32<1>, cudaFuncAttributeMaxDynamicSharedMemorySize, TGEMM_SMEM);

    // 0) round operands to tf32 (removes truncation bias in the mma)
    {
        int n4 = (MROWS * DIM) / 4;
        round_tf32<<<(n4 + 255) / 256, 256>>>(x, xr, n4);
        int w4 = (QKVDIM * DIM) / 4;
        round_tf32<<<(w4 + 255) / 256, 256>>>(w_qkv, wqr, w4);
        int p4 = (DIM * DIM) / 4;
        round_tf32<<<(p4 + 255) / 256, 256>>>(w_proj, wpr, p4);
    }
    // 1) QKV GEMM (tf32) -> q/k/vt bf16 hi/lo planes (q pre-scaled)
    {
        dim3 grid(QKVDIM / 128, MROWS / 128);   // 6 x 1024
        gemm_tf32<0><<<grid, 256, TGEMM_SMEM>>>(xr, wqr, b_qkv, nullptr);
    }
    // 2) windowed attention (bf16 HMMA) -> g_ao (tf32-rounded fp32)
    attn_mma<<<B_WIN * NHEADS, 128>>>(mask, bias_table);
    // 3) output projection (tf32) -> out
    {
        dim3 grid(DIM / 128, MROWS / 128);      // 2 x 1024
        gemm_tf32<1><<<grid, 256, TGEMM_SMEM>>>(ao, wpr, b_proj, out);
    }
}

// round 11
// speedup vs baseline: 1.2771x; 1.0220x over previous
#include <cuda_runtime.h>
#include <cuda_bf16.h>
#include <cstdint>

#define B_WIN   2048
#define NTOK    64
#define DIM     256
#define NHEADS  8
#define QKVDIM  768
#define MROWS   (B_WIN * NTOK)          // 131072
#define SCALE   0.17677669529663687f    // 32^-0.5

// ---------------- scratch (device globals; no cudaMalloc allowed) ----------
#define HEAD_ELEMS (2048ull * 8ull * 64ull * 32ull)
__device__ __nv_bfloat16 g_q_hi[HEAD_ELEMS],  g_q_lo[HEAD_ELEMS];
__device__ __nv_bfloat16 g_k_hi[HEAD_ELEMS],  g_k_lo[HEAD_ELEMS];
__device__ __nv_bfloat16 g_vt_hi[HEAD_ELEMS], g_vt_lo[HEAD_ELEMS];  // [bh][d][n]
__device__ float g_ao[(size_t)MROWS * DIM];    // tf32-rounded attention out
__device__ float g_wqr[QKVDIM * DIM];          // tf32-rounded w_qkv
__device__ float g_wpr[DIM * DIM];             // tf32-rounded w_proj

// ================= helpers ==================================================
__device__ __forceinline__ uint32_t smem_u32(const void* p) {
    uint32_t a;
    asm("{ .reg .u64 t; cvta.to.shared.u64 t, %1; cvt.u32.u64 %0, t; }"
        : "=r"(a) : "l"(p));
    return a;
}

__device__ __forceinline__ void ldsm_x4(uint32_t* r, uint32_t addr) {
    asm volatile("ldmatrix.sync.aligned.m8n8.x4.shared.b16 {%0,%1,%2,%3}, [%4];"
                 : "=r"(r[0]), "=r"(r[1]), "=r"(r[2]), "=r"(r[3]) : "r"(addr));
}

// bf16 k16 mma (attention path)
__device__ __forceinline__ void mma16816(float* c, const uint32_t* a, const uint32_t* b) {
    asm volatile("mma.sync.aligned.m16n8k16.row.col.f32.bf16.bf16.f32 "
                 "{%0,%1,%2,%3}, {%4,%5,%6,%7}, {%8,%9}, {%0,%1,%2,%3};"
                 : "+f"(c[0]), "+f"(c[1]), "+f"(c[2]), "+f"(c[3])
                 : "r"(a[0]), "r"(a[1]), "r"(a[2]), "r"(a[3]),
                   "r"(b[0]), "r"(b[1]));
}

// tf32 k8 mma (GEMM path)
__device__ __forceinline__ void mma1688(float* c, const uint32_t* a,
                                        uint32_t b0, uint32_t b1) {
    asm volatile("mma.sync.aligned.m16n8k8.row.col.f32.tf32.tf32.f32 "
                 "{%0,%1,%2,%3}, {%4,%5,%6,%7}, {%8,%9}, {%0,%1,%2,%3};"
                 : "+f"(c[0]), "+f"(c[1]), "+f"(c[2]), "+f"(c[3])
                 : "r"(a[0]), "r"(a[1]), "r"(a[2]), "r"(a[3]),
                   "r"(b0), "r"(b1));
}

__device__ __forceinline__ float tf32r(float f) {
    uint32_t u;
    asm("cvt.rna.tf32.f32 %0, %1;" : "=r"(u) : "f"(f));
    return __uint_as_float(u);
}
__device__ __forceinline__ uint32_t tf32r_bits(uint32_t fb) {
    uint32_t u;
    asm("cvt.rna.tf32.f32 %0, %1;" : "=r"(u) : "f"(__uint_as_float(fb)));
    return u;
}

__device__ __forceinline__ uint32_t pack_bf16x2(float x, float y) {
    __nv_bfloat162 t = __floats2bfloat162_rn(x, y);
    return *(uint32_t*)&t;
}

__device__ __forceinline__ void cp16(uint32_t dst, const void* src) {
    asm volatile("cp.async.cg.shared.global [%0], [%1], 16;"
                 :: "r"(dst), "l"(src) : "memory");
}
#define CP_COMMIT() asm volatile("cp.async.commit_group;" ::: "memory")

// ================= fp32 -> tf32-rounded fp32 (weights only) ================
__global__ void round_tf32(const float* __restrict__ src,
                           float* __restrict__ dst, int n4)
{
    int i = blockIdx.x * blockDim.x + threadIdx.x;
    if (i >= n4) return;
    float4 v = ((const float4*)src)[i];
    v.x = tf32r(v.x); v.y = tf32r(v.y); v.z = tf32r(v.z); v.w = tf32r(v.w);
    ((float4*)dst)[i] = v;
}

// ================= TF32 GEMM (3-stage cp.async + LDSM fragments) ============
// C[128 x 128] = A[128 x 256] * W[128 x 256]^T  (1-pass tf32)
// A is RAW fp32: fragments rounded in-register (cvt.rna) after LDSM.
// W is pre-rounded. 8 warps 4(M)x2(N), warp tile 32x64, BK=32, 3 stages,
// ONE __syncthreads per K-chunk (stage reuse distance = 3).

#define TSTRW  36                   // fp32 words per smem row (144B, conflict-free)
#define T_A    0
#define T_B    18432                // 128*36*4
#define TSTAGE 36864
#define TGEMM_SMEM (3 * TSTAGE)     // 110592 bytes

template <int MODE>
__global__ void __launch_bounds__(256, 2)
gemm_tf32(const float* __restrict__ A, const float* __restrict__ W,
          const float* __restrict__ bias, float* __restrict__ out)
{
    extern __shared__ char smem[];
    const uint32_t sb = smem_u32(smem);

    const int tid  = threadIdx.x;
    const int lane = tid & 31;
    const int warp = tid >> 5;
    const int wm   = warp >> 1;          // 0..3
    const int wn   = warp & 1;           // 0..1
    const int row0 = blockIdx.y * 128;
    const int col0 = blockIdx.x * 128;

    float acc[2][8][4];
#pragma unroll
    for (int a = 0; a < 2; a++)
#pragma unroll
        for (int b = 0; b < 8; b++)
#pragma unroll
            for (int c = 0; c < 4; c++) acc[a][b][c] = 0.f;

    const int gid = lane >> 2, tig = lane & 3;

    auto issue = [&](int kc) {
        const uint32_t stb = sb + (kc % 3) * TSTAGE;
        const int k0 = kc * 32;
#pragma unroll
        for (int t = 0; t < 4; t++) {
            const int idx = tid + t * 256;
            const int r = idx >> 3, c8 = idx & 7;
            const uint32_t so = (uint32_t)r * 144 + c8 * 16;
            cp16(stb + T_A + so, A + (size_t)(row0 + r) * 256 + k0 + c8 * 4);
            cp16(stb + T_B + so, W + (size_t)(col0 + r) * 256 + k0 + c8 * 4);
        }
        CP_COMMIT();
    };

    issue(0);
    issue(1);

    // ldsm lane addressing:
    // A matrices: (rows 0-7 / 8-15) x (k 0-3 / 4-7)
    // B matrices: (rows 0-7: k 0-3, k 4-7), (rows 8-15: k 0-3, k 4-7)
    const int lg = lane >> 3, lrw = lane & 7;
    const uint32_t a_ld = (uint32_t)((wm * 32 + ((lg & 1) << 3) + lrw) * TSTRW
                                     + ((lg >> 1) << 2)) * 4;
    const uint32_t b_ld = (uint32_t)((wn * 64 + ((lg >> 1) << 3) + lrw) * TSTRW
                                     + ((lg & 1) << 2)) * 4;

    for (int kc = 0; kc < 8; kc++) {
        if (kc < 7) {
            asm volatile("cp.async.wait_group 1;" ::: "memory");
        } else {
            asm volatile("cp.async.wait_group 0;" ::: "memory");
        }
        __syncthreads();                 // stage kc ready; stage (kc+2)%3 free
        if (kc + 2 < 8) issue(kc + 2);

        const uint32_t sA = sb + (kc % 3) * TSTAGE + T_A;
        const uint32_t sB = sb + (kc % 3) * TSTAGE + T_B;

#pragma unroll
        for (int ks = 0; ks < 4; ks++) {
            const uint32_t kso = (uint32_t)(ks * 8) * 4;
            uint32_t af[2][4], bf[4][4];
#pragma unroll
            for (int mt = 0; mt < 2; mt++) {
                ldsm_x4(af[mt], sA + a_ld + mt * 16 * TSTRW * 4 + kso);
#pragma unroll
                for (int i = 0; i < 4; i++)       // round raw fp32 A -> tf32
                    af[mt][i] = tf32r_bits(af[mt][i]);
            }
#pragma unroll
            for (int p = 0; p < 4; p++)
                ldsm_x4(bf[p], sB + b_ld + p * 16 * TSTRW * 4 + kso);
#pragma unroll
            for (int mt = 0; mt < 2; mt++)
#pragma unroll
                for (int nt = 0; nt < 8; nt++) {
                    const uint32_t* bb = &bf[nt >> 1][(nt & 1) * 2];
                    mma1688(acc[mt][nt], af[mt], bb[0], bb[1]);
                }
        }
    }

    // ---- epilogue -------------------------------------------------------------
#pragma unroll
    for (int mt = 0; mt < 2; mt++)
#pragma unroll
        for (int nt = 0; nt < 8; nt++) {
            const int col = col0 + wn * 64 + nt * 8 + tig * 2;
            const float2 bv = *(const float2*)(bias + col);
#pragma unroll
            for (int rs = 0; rs < 2; rs++) {
                const int row = row0 + wm * 32 + mt * 16 + gid + rs * 8;
                float v0 = acc[mt][nt][rs * 2 + 0] + bv.x;
                float v1 = acc[mt][nt][rs * 2 + 1] + bv.y;
                if (MODE == 0) {
                    const int s = col >> 8;
                    if (s == 0) { v0 *= SCALE; v1 *= SCALE; }
                    __nv_bfloat16 h0 = __float2bfloat16(v0);
                    __nv_bfloat16 l0 = __float2bfloat16(v0 - __bfloat162float(h0));
                    __nv_bfloat16 h1 = __float2bfloat16(v1);
                    __nv_bfloat16 l1 = __float2bfloat16(v1 - __bfloat162float(h1));
                    const int hh = (col >> 5) & 7, d = col & 31;
                    const int b = row >> 6, n = row & 63;
                    const size_t pb = (size_t)(b * 8 + hh) * 2048;
                    if (s == 0) {
                        *(__nv_bfloat162*)(g_q_hi + pb + n * 32 + d) = __halves2bfloat162(h0, h1);
                        *(__nv_bfloat162*)(g_q_lo + pb + n * 32 + d) = __halves2bfloat162(l0, l1);
                    } else if (s == 1) {
                        *(__nv_bfloat162*)(g_k_hi + pb + n * 32 + d) = __halves2bfloat162(h0, h1);
                        *(__nv_bfloat162*)(g_k_lo + pb + n * 32 + d) = __halves2bfloat162(l0, l1);
                    } else {   // v, stored transposed [d][n]
                        g_vt_hi[pb + (size_t)d * 64 + n]       = h0;
                        g_vt_hi[pb + (size_t)(d + 1) * 64 + n] = h1;
                        g_vt_lo[pb + (size_t)d * 64 + n]       = l0;
                        g_vt_lo[pb + (size_t)(d + 1) * 64 + n] = l1;
                    }
                } else {
                    *(float2*)(out + (size_t)row * 256 + col)
                        = make_float2(v0, v1);
                }
            }
        }
}

// ================= HMMA attention: one (window, head) per CTA ===============
#define QSTR 40
#define VSTR 72

__global__ void __launch_bounds__(128)
attn_mma(const float* __restrict__ mask, const float* __restrict__ bias_table)
{
    const int bh = blockIdx.x;
    const int b  = bh >> 3;
    const int h  = bh & 7;

    __shared__ __nv_bfloat16 sQh[64 * QSTR], sQl[64 * QSTR];
    __shared__ __nv_bfloat16 sKh[64 * QSTR], sKl[64 * QSTR];
    __shared__ __nv_bfloat16 sVh[32 * VSTR], sVl[32 * VSTR];
    __shared__ float bt[228];

    const int tid  = threadIdx.x;
    const int warp = tid >> 5;
    const int lane = tid & 31;

    const __nv_bfloat16* Qh = g_q_hi  + (size_t)bh * 2048;
    const __nv_bfloat16* Ql = g_q_lo  + (size_t)bh * 2048;
    const __nv_bfloat16* Kh = g_k_hi  + (size_t)bh * 2048;
    const __nv_bfloat16* Kl = g_k_lo  + (size_t)bh * 2048;
    const __nv_bfloat16* Vh = g_vt_hi + (size_t)bh * 2048;
    const __nv_bfloat16* Vl = g_vt_lo + (size_t)bh * 2048;

    for (int c = tid; c < 256; c += 128) {
        const int qr = c >> 2, qc = (c & 3) * 8;
        *(uint4*)(sQh + qr * QSTR + qc) = *(const uint4*)(Qh + c * 8);
        *(uint4*)(sQl + qr * QSTR + qc) = *(const uint4*)(Ql + c * 8);
        *(uint4*)(sKh + qr * QSTR + qc) = *(const uint4*)(Kh + c * 8);
        *(uint4*)(sKl + qr * QSTR + qc) = *(const uint4*)(Kl + c * 8);
        const int vr = c >> 3, vc = (c & 7) * 8;
        *(uint4*)(sVh + vr * VSTR + vc) = *(const uint4*)(Vh + c * 8);
        *(uint4*)(sVl + vr * VSTR + vc) = *(const uint4*)(Vl + c * 8);
    }
    for (int t = tid; t < 225; t += 128) bt[t] = bias_table[t * NHEADS + h];
    __syncthreads();

    const int gid = lane >> 2, tig = lane & 3;
    const int a_rowoff = (warp * 16 + (lane & 15)) * QSTR + (lane >> 4) * 8;
    const int b_row    = ((lane >> 4) << 3) + (lane & 7);
    const int b_ksel   = ((lane >> 3) & 1) << 3;

    // ---- QK^T ------------------------------------------------------------------
    float acc[8][4];
#pragma unroll
    for (int nt = 0; nt < 8; nt++)
#pragma unroll
        for (int c = 0; c < 4; c++) acc[nt][c] = 0.f;

#pragma unroll
    for (int kt = 0; kt < 2; kt++) {
        uint32_t qh[4], ql[4];
        ldsm_x4(qh, smem_u32(sQh + a_rowoff + kt * 16));
        ldsm_x4(ql, smem_u32(sQl + a_rowoff + kt * 16));
#pragma unroll
        for (int ng = 0; ng < 4; ng++) {
            uint32_t kh[4], kl[4];
            const int off = (ng * 16 + b_row) * QSTR + kt * 16 + b_ksel;
            ldsm_x4(kh, smem_u32(sKh + off));
            ldsm_x4(kl, smem_u32(sKl + off));
#pragma unroll
            for (int j = 0; j < 2; j++) {
                float* c = acc[ng * 2 + j];
                mma16816(c, qh, &kh[j * 2]);
                mma16816(c, qh, &kl[j * 2]);
                mma16816(c, ql, &kh[j * 2]);
            }
        }
    }

    // ---- bias + mask ----------------------------------------------------------
    const int i0 = warp * 16 + gid, i1 = i0 + 8;
    const int yi0 = i0 >> 3, xi0 = i0 & 7;
    const int yi1 = i1 >> 3, xi1 = i1 & 7;
    const float* mrow = mask + (size_t)b * 4096;
#pragma unroll
    for (int nt = 0; nt < 8; nt++) {
        const int col = nt * 8 + tig * 2;
        const float2 m0 = *(const float2*)(mrow + i0 * 64 + col);
        const float2 m1 = *(const float2*)(mrow + i1 * 64 + col);
        acc[nt][0] += bt[(yi0 - nt + 7) * 15 + (xi0 - tig * 2 + 7)] + m0.x;
        acc[nt][1] += bt[(yi0 - nt + 7) * 15 + (xi0 - tig * 2 + 6)] + m0.y;
        acc[nt][2] += bt[(yi1 - nt + 7) * 15 + (xi1 - tig * 2 + 7)] + m1.x;
        acc[nt][3] += bt[(yi1 - nt + 7) * 15 + (xi1 - tig * 2 + 6)] + m1.y;
    }

    // ---- softmax ---------------------------------------------------------------
    float mx0 = -1e30f, mx1 = -1e30f;
#pragma unroll
    for (int nt = 0; nt < 8; nt++) {
        mx0 = fmaxf(mx0, fmaxf(acc[nt][0], acc[nt][1]));
        mx1 = fmaxf(mx1, fmaxf(acc[nt][2], acc[nt][3]));
    }
    mx0 = fmaxf(mx0, __shfl_xor_sync(0xffffffffu, mx0, 1));
    mx0 = fmaxf(mx0, __shfl_xor_sync(0xffffffffu, mx0, 2));
    mx1 = fmaxf(mx1, __shfl_xor_sync(0xffffffffu, mx1, 1));
    mx1 = fmaxf(mx1, __shfl_xor_sync(0xffffffffu, mx1, 2));

    float sum0 = 0.f, sum1 = 0.f;
#pragma unroll
    for (int nt = 0; nt < 8; nt++) {
        acc[nt][0] = __expf(acc[nt][0] - mx0);
        acc[nt][1] = __expf(acc[nt][1] - mx0);
        acc[nt][2] = __expf(acc[nt][2] - mx1);
        acc[nt][3] = __expf(acc[nt][3] - mx1);
        sum0 += acc[nt][0] + acc[nt][1];
        sum1 += acc[nt][2] + acc[nt][3];
    }
    sum0 += __shfl_xor_sync(0xffffffffu, sum0, 1);
    sum0 += __shfl_xor_sync(0xffffffffu, sum0, 2);
    sum1 += __shfl_xor_sync(0xffffffffu, sum1, 1);
    sum1 += __shfl_xor_sync(0xffffffffu, sum1, 2);
    const float inv0 = 1.f / sum0, inv1 = 1.f / sum1;

    // ---- repack P into A-fragments (hi/lo split) --------------------------------
    uint32_t phi[4][4], plo[4][4];
#pragma unroll
    for (int kt = 0; kt < 4; kt++) {
        const float f[4][2] = {
            {acc[kt*2][0] * inv0,   acc[kt*2][1] * inv0},
            {acc[kt*2][2] * inv1,   acc[kt*2][3] * inv1},
            {acc[kt*2+1][0] * inv0, acc[kt*2+1][1] * inv0},
            {acc[kt*2+1][2] * inv1, acc[kt*2+1][3] * inv1}};
#pragma unroll
        for (int r = 0; r < 4; r++) {
            __nv_bfloat16 hx = __float2bfloat16(f[r][0]);
            __nv_bfloat16 hy = __float2bfloat16(f[r][1]);
            phi[kt][r] = pack_bf16x2(f[r][0], f[r][1]);
            plo[kt][r] = pack_bf16x2(f[r][0] - __bfloat162float(hx),
                                     f[r][1] - __bfloat162float(hy));
        }
    }

    // ---- P * V -------------------------------------------------------------------
    float ao[4][4];
#pragma unroll
    for (int dn = 0; dn < 4; dn++)
#pragma unroll
        for (int c = 0; c < 4; c++) ao[dn][c] = 0.f;

#pragma unroll
    for (int kt = 0; kt < 4; kt++) {
#pragma unroll
        for (int g = 0; g < 2; g++) {
            uint32_t vh[4], vl[4];
            const int off = (g * 16 + b_row) * VSTR + kt * 16 + b_ksel;
            ldsm_x4(vh, smem_u32(sVh + off));
            ldsm_x4(vl, smem_u32(sVl + off));
#pragma unroll
            for (int j = 0; j < 2; j++) {
                float* c = ao[g * 2 + j];
                mma16816(c, phi[kt], &vh[j * 2]);
                mma16816(c, phi[kt], &vl[j * 2]);
                mma16816(c, plo[kt], &vh[j * 2]);
            }
        }
    }

    // ---- epilogue: tf32-rounded fp32 for the proj GEMM --------------------------
#pragma unroll
    for (int dn = 0; dn < 4; dn++) {
        const int d = dn * 8 + tig * 2;
#pragma unroll
        for (int rs = 0; rs < 2; rs++) {
            const int row = rs ? i1 : i0;
            const float v0 = tf32r(ao[dn][rs * 2 + 0]);
            const float v1 = tf32r(ao[dn][rs * 2 + 1]);
            const size_t o = ((size_t)b * 64 + row) * DIM + h * 32 + d;
            *(float2*)(g_ao + o) = make_float2(v0, v1);
        }
    }
}

// ---------------- launch ----------------------------------------------------
extern "C" void kernel_launch(void* const* d_in, const int* in_sizes, int n_in,
                              void* d_out, int out_size)
{
    const float* x          = (const float*)d_in[0]; // (2048,64,256)
    const float* mask       = (const float*)d_in[1]; // (2048,1,64,64)
    const float* w_qkv      = (const float*)d_in[2]; // (768,256)
    const float* b_qkv      = (const float*)d_in[3]; // (768)
    const float* w_proj     = (const float*)d_in[4]; // (256,256)
    const float* b_proj     = (const float*)d_in[5]; // (256)
    const float* bias_table = (const float*)d_in[6]; // (225,8)
    float* out = (float*)d_out;                      // (2048,64,256)

    (void)in_sizes; (void)n_in; (void)out_size;

    float *ao, *wqr, *wpr;
    cudaGetSymbolAddress((void**)&ao,  g_ao);
    cudaGetSymbolAddress((void**)&wqr, g_wqr);
    cudaGetSymbolAddress((void**)&wpr, g_wpr);

    cudaFuncSetAttribute(gemm_tf32<0>, cudaFuncAttributeMaxDynamicSharedMemorySize, TGEMM_SMEM);
    cudaFuncSetAttribute(gemm_tf32<1>, cudaFuncAttributeMaxDynamicSharedMemorySize, TGEMM_SMEM);

    // 0) round weights to tf32 (x is rounded in-register inside the GEMM)
    {
        int w4 = (QKVDIM * DIM) / 4;
        round_tf32<<<(w4 + 255) / 256, 256>>>(w_qkv, wqr, w4);
        int p4 = (DIM * DIM) / 4;
        round_tf32<<<(p4 + 255) / 256, 256>>>(w_proj, wpr, p4);
    }
    // 1) QKV GEMM (tf32) -> q/k/vt bf16 hi/lo planes (q pre-scaled)
    {
        dim3 grid(QKVDIM / 128, MROWS / 128);   // 6 x 1024
        gemm_tf32<0><<<grid, 256, TGEMM_SMEM>>>(x, wqr, b_qkv, nullptr);
    }
    // 2) windowed attention (bf16 HMMA) -> g_ao (tf32-rounded fp32)
    attn_mma<<<B_WIN * NHEADS, 128>>>(mask, bias_table);
    // 3) output projection (tf32) -> out
    {
        dim3 grid(DIM / 128, MROWS / 128);      // 2 x 1024
        gemm_tf32<1><<<grid, 256, TGEMM_SMEM>>>(ao, wpr, b_proj, out);
    }
}